// round 1
// baseline (speedup 1.0000x reference)
#include <cuda_runtime.h>
#include <cstdint>
#include <cstddef>

#define N_NODES 100000
#define N_EDGES 1600000
#define IN_DIM 256
#define OUT_DIM 64

// Scratch for pre_sup[2][N_NODES][OUT_DIM] (51.2 MB). __device__ global: no alloc.
__device__ float g_presup[2ULL * N_NODES * OUT_DIM];

// ---------------------------------------------------------------------------
// Fused GEMM: pre[s][m][n] = sum_k x[m][k] * W[s][k][n], both supports at once.
// Block tile 128 rows x 128 cols (cols = 2 supports x 64), 256 threads,
// 8x8 microtile per thread.
// ---------------------------------------------------------------------------
#define BM 128
#define BN 128
#define KC 16
#define APAD 4
#define BPAD 4

__global__ __launch_bounds__(256, 1) void gemm_kernel(const float* __restrict__ x,
                                                      const float* __restrict__ W) {
    __shared__ float As[KC][BM + APAD];
    __shared__ float Bs[KC][BN + BPAD];
    const int tid = threadIdx.x;
    const int m0 = blockIdx.x * BM;
    const int tx = tid & 15;   // column group (8 cols each)
    const int ty = tid >> 4;   // row group (8 rows each)

    float acc[8][8];
#pragma unroll
    for (int i = 0; i < 8; i++)
#pragma unroll
        for (int j = 0; j < 8; j++) acc[i][j] = 0.f;

    for (int k0 = 0; k0 < IN_DIM; k0 += KC) {
        // Load A tile: 128 rows x 16 k, transposed into As[k][row].
#pragma unroll
        for (int it = 0; it < 2; it++) {
            int idx = tid + it * 256;        // 0..511
            int row = idx >> 2;              // 0..127
            int kq  = (idx & 3) * 4;         // 0,4,8,12
            float4 v = make_float4(0.f, 0.f, 0.f, 0.f);
            if (m0 + row < N_NODES)
                v = *reinterpret_cast<const float4*>(
                        x + (size_t)(m0 + row) * IN_DIM + k0 + kq);
            As[kq + 0][row] = v.x;
            As[kq + 1][row] = v.y;
            As[kq + 2][row] = v.z;
            As[kq + 3][row] = v.w;
        }
        // Load B tile: 16 k x 128 cols (sup0 cols 0..63, sup1 cols 64..127).
#pragma unroll
        for (int it = 0; it < 2; it++) {
            int idx = tid + it * 256;
            int kk  = idx >> 5;              // 0..15
            int cw  = (idx & 31) * 4;        // 0..124 step 4
            int s   = cw >> 6;
            int n   = cw & 63;
            float4 v = *reinterpret_cast<const float4*>(
                           W + ((size_t)s * IN_DIM + (k0 + kk)) * OUT_DIM + n);
            *reinterpret_cast<float4*>(&Bs[kk][cw]) = v;
        }
        __syncthreads();

#pragma unroll
        for (int kk = 0; kk < KC; kk++) {
            float a[8], b[8];
            *reinterpret_cast<float4*>(a)     = *reinterpret_cast<const float4*>(&As[kk][ty * 8]);
            *reinterpret_cast<float4*>(a + 4) = *reinterpret_cast<const float4*>(&As[kk][ty * 8 + 4]);
            *reinterpret_cast<float4*>(b)     = *reinterpret_cast<const float4*>(&Bs[kk][tx * 8]);
            *reinterpret_cast<float4*>(b + 4) = *reinterpret_cast<const float4*>(&Bs[kk][tx * 8 + 4]);
#pragma unroll
            for (int i = 0; i < 8; i++)
#pragma unroll
                for (int j = 0; j < 8; j++) acc[i][j] += a[i] * b[j];
        }
        __syncthreads();
    }

    // Store: columns [tx*8, tx*8+8) belong to a single support (boundary at 64).
    const int col = tx * 8;
    const int s   = col >> 6;
    const int n   = col & 63;
#pragma unroll
    for (int i = 0; i < 8; i++) {
        int row = m0 + ty * 8 + i;
        if (row < N_NODES) {
            float* dst = g_presup + ((size_t)s * N_NODES + row) * OUT_DIM + n;
            *reinterpret_cast<float4*>(dst) =
                make_float4(acc[i][0], acc[i][1], acc[i][2], acc[i][3]);
            *reinterpret_cast<float4*>(dst + 4) =
                make_float4(acc[i][4], acc[i][5], acc[i][6], acc[i][7]);
        }
    }
}

// ---------------------------------------------------------------------------
// SpMM scatter: half-warp (16 lanes) per edge, float4 per lane (64 floats).
// out[dst] += val * pre_sup[sup][src] via red.global.add.v4.f32 (no-return).
// Edge arrays are [2][E] contiguous, so a flat index e covers both supports.
// ---------------------------------------------------------------------------
__global__ __launch_bounds__(256) void spmm_kernel(const float* __restrict__ edge_val,
                                                   const int* __restrict__ edge_src,
                                                   const int* __restrict__ edge_dst,
                                                   float* __restrict__ out) {
    long long t = (long long)blockIdx.x * 256 + threadIdx.x;
    long long e = t >> 4;
    if (e >= 2LL * N_EDGES) return;
    const int lane16 = (int)(t & 15);

    const float val = __ldg(edge_val + e);
    const int   src = __ldg(edge_src + e);
    const int   dst = __ldg(edge_dst + e);
    const int   sup = (e >= (long long)N_EDGES) ? 1 : 0;

    const float4 g = *reinterpret_cast<const float4*>(
        g_presup + ((size_t)sup * N_NODES + src) * OUT_DIM + lane16 * 4);

    float* oa = out + (size_t)dst * OUT_DIM + lane16 * 4;
    asm volatile("red.global.add.v4.f32 [%0], {%1, %2, %3, %4};"
                 :: "l"(oa),
                    "f"(g.x * val), "f"(g.y * val), "f"(g.z * val), "f"(g.w * val)
                 : "memory");
}

// ---------------------------------------------------------------------------
// ReLU epilogue over out (float4-vectorized).
// ---------------------------------------------------------------------------
__global__ __launch_bounds__(256) void relu_kernel(float* __restrict__ out) {
    int i = blockIdx.x * 256 + threadIdx.x;
    const int n4 = N_NODES * OUT_DIM / 4;
    if (i < n4) {
        float4* p = reinterpret_cast<float4*>(out) + i;
        float4 v = *p;
        v.x = fmaxf(v.x, 0.f);
        v.y = fmaxf(v.y, 0.f);
        v.z = fmaxf(v.z, 0.f);
        v.w = fmaxf(v.w, 0.f);
        *p = v;
    }
}

extern "C" void kernel_launch(void* const* d_in, const int* in_sizes, int n_in,
                              void* d_out, int out_size) {
    const float* x        = (const float*)d_in[0];
    const float* W        = (const float*)d_in[1];
    const float* edge_val = (const float*)d_in[2];
    const int*   edge_src = (const int*)d_in[3];
    const int*   edge_dst = (const int*)d_in[4];
    float*       out      = (float*)d_out;

    // out is poisoned by the harness; atomics need zeros.
    cudaMemsetAsync(out, 0, (size_t)N_NODES * OUT_DIM * sizeof(float), 0);

    gemm_kernel<<<(N_NODES + BM - 1) / BM, 256>>>(x, W);

    long long total = 2LL * N_EDGES * 16;            // 16 lanes per edge
    int blocks = (int)((total + 255) / 256);
    spmm_kernel<<<blocks, 256>>>(edge_val, edge_src, edge_dst, out);

    relu_kernel<<<(N_NODES * OUT_DIM / 4 + 255) / 256, 256>>>(out);
}

// round 3
// speedup vs baseline: 1.3264x; 1.3264x over previous
#include <cuda_runtime.h>
#include <cuda_bf16.h>
#include <cstdint>
#include <cstddef>

#define N_NODES 100000
#define N_EDGES 1600000
#define IN_DIM 256
#define OUT_DIM 64

// Scratch (no allocations allowed): pre_sup[2][N][64] fp32 + W^T bf16 hi/lo.
__device__ float g_presup[2ULL * N_NODES * OUT_DIM];
__device__ __nv_bfloat16 g_Wb_hi[128 * 256];   // [n = sup*64 + j][k]
__device__ __nv_bfloat16 g_Wb_lo[128 * 256];

// ---------------------------------------------------------------------------
// W conversion: W[2][256][64] fp32 -> W^T bf16 hi/lo, [n][k] layout
// ---------------------------------------------------------------------------
__global__ void wconv_kernel(const float* __restrict__ W) {
    int t = blockIdx.x * 256 + threadIdx.x;
    if (t >= 128 * 256) return;
    int n = t >> 8, k = t & 255;
    int s = n >> 6, j = n & 63;
    float f = W[((size_t)s * IN_DIM + k) * OUT_DIM + j];
    __nv_bfloat16 h = __float2bfloat16(f);
    float lo = f - __bfloat162float(h);
    g_Wb_hi[t] = h;
    g_Wb_lo[t] = __float2bfloat16(lo);
}

// ---------------------------------------------------------------------------
// HMMA GEMM: pre[s][m][n] = x[m][:] @ W[s][:][n], bf16 split emulation.
// CTA: 256 threads = 8 warps, each warp owns m16 x n128. K=256 in 16 k16 steps.
// B (W^T hi/lo) fully SMEM-resident; A fragments straight from gmem with a
// one-step software pipeline.
// ---------------------------------------------------------------------------
#define BS_STRIDE 264                       // 256 + 8 bf16 pad (row = 528 B)
#define BS_BYTES  (128 * BS_STRIDE * 2)     // one operand: 67584 B
#define SMEM_BYTES (2 * BS_BYTES)           // 135168 B

__device__ __forceinline__ uint32_t smem_u32(const void* p) {
    uint32_t a;
    asm("{ .reg .u64 t; cvta.to.shared.u64 t, %1; cvt.u32.u64 %0, t; }" : "=r"(a) : "l"(p));
    return a;
}

__device__ __forceinline__ void ldsm4(uint32_t& d0, uint32_t& d1, uint32_t& d2,
                                      uint32_t& d3, uint32_t addr) {
    asm volatile("ldmatrix.sync.aligned.m8n8.x4.shared.b16 {%0,%1,%2,%3}, [%4];"
                 : "=r"(d0), "=r"(d1), "=r"(d2), "=r"(d3) : "r"(addr));
}

__device__ __forceinline__ void mma16816(float* c, uint32_t a0, uint32_t a1,
                                         uint32_t a2, uint32_t a3,
                                         uint32_t b0, uint32_t b1) {
    asm volatile(
        "mma.sync.aligned.m16n8k16.row.col.f32.bf16.bf16.f32 "
        "{%0,%1,%2,%3}, {%4,%5,%6,%7}, {%8,%9}, {%0,%1,%2,%3};"
        : "+f"(c[0]), "+f"(c[1]), "+f"(c[2]), "+f"(c[3])
        : "r"(a0), "r"(a1), "r"(a2), "r"(a3), "r"(b0), "r"(b1));
}

__device__ __forceinline__ uint32_t pack_hi(float a, float b) {
    __nv_bfloat162 h = __floats2bfloat162_rn(a, b);
    return *reinterpret_cast<uint32_t*>(&h);
}
__device__ __forceinline__ uint32_t pack_lo(float a, float b, uint32_t hi) {
    __nv_bfloat162 h = *reinterpret_cast<__nv_bfloat162*>(&hi);
    __nv_bfloat162 l = __floats2bfloat162_rn(a - __bfloat162float(h.x),
                                             b - __bfloat162float(h.y));
    return *reinterpret_cast<uint32_t*>(&l);
}

__global__ __launch_bounds__(256, 1) void gemm_hmma(const float* __restrict__ x) {
    extern __shared__ __align__(16) char smem[];
    const uint32_t sBhi = smem_u32(smem);
    const uint32_t sBlo = sBhi + BS_BYTES;
    const int tid = threadIdx.x;
    const int wid = tid >> 5;
    const int lane = tid & 31;

    // --- Stage all of W^T (hi/lo) into padded SMEM ---
#pragma unroll 4
    for (int it = 0; it < 16; it++) {
        int idx = it * 256 + tid;            // 4096 uint4 per operand
        int n = idx >> 5;
        int kq = (idx & 31) * 8;
        uint32_t off = (uint32_t)(n * BS_STRIDE + kq) * 2;
        *reinterpret_cast<uint4*>(smem + off) =
            *reinterpret_cast<const uint4*>(g_Wb_hi + n * 256 + kq);
        *reinterpret_cast<uint4*>(smem + BS_BYTES + off) =
            *reinterpret_cast<const uint4*>(g_Wb_lo + n * 256 + kq);
    }
    __syncthreads();

    // --- Per-warp A rows ---
    const int m_base = blockIdx.x * 128 + wid * 16;
    const int r0 = m_base + (lane >> 2);
    const int r1 = r0 + 8;
    const bool p0 = r0 < N_NODES;
    const bool p1 = r1 < N_NODES;
    const float* x0 = x + (size_t)(p0 ? r0 : 0) * IN_DIM;
    const float* x1 = x + (size_t)(p1 ? r1 : 0) * IN_DIM;
    const int klane = (lane & 3) * 2;

    // --- Per-thread ldmatrix address bases (B) ---
    const int grp = lane >> 3;
    const int lrow = lane & 7;
    const uint32_t b_off = (uint32_t)((lrow + ((grp & 2) << 2)) * BS_STRIDE +
                                      ((grp & 1) << 3)) * 2;

    float acc[16][4];
#pragma unroll
    for (int i = 0; i < 16; i++)
#pragma unroll
        for (int j = 0; j < 4; j++) acc[i][j] = 0.f;

    // Software pipeline: raw A for current k-step already loaded.
    float2 raw[4];
    raw[0] = *reinterpret_cast<const float2*>(x0 + klane);
    raw[1] = *reinterpret_cast<const float2*>(x1 + klane);
    raw[2] = *reinterpret_cast<const float2*>(x0 + klane + 8);
    raw[3] = *reinterpret_cast<const float2*>(x1 + klane + 8);

    for (int kk = 0; kk < 16; kk++) {
        float2 nxt[4];
        if (kk < 15) {
            int k0 = (kk + 1) * 16 + klane;
            nxt[0] = *reinterpret_cast<const float2*>(x0 + k0);
            nxt[1] = *reinterpret_cast<const float2*>(x1 + k0);
            nxt[2] = *reinterpret_cast<const float2*>(x0 + k0 + 8);
            nxt[3] = *reinterpret_cast<const float2*>(x1 + k0 + 8);
        }

        uint32_t ah[4], al[4];
#pragma unroll
        for (int i = 0; i < 4; i++) {
            ah[i] = pack_hi(raw[i].x, raw[i].y);
            al[i] = pack_lo(raw[i].x, raw[i].y, ah[i]);
        }

        const uint32_t kbyte = (uint32_t)(kk * 16) * 2 + b_off;
#pragma unroll
        for (int np = 0; np < 8; np++) {
            const uint32_t boff = kbyte + (uint32_t)(np * 16 * BS_STRIDE) * 2;
            uint32_t bh0, bh1, bh2, bh3, bl0, bl1, bl2, bl3;
            ldsm4(bh0, bh1, bh2, bh3, sBhi + boff);
            ldsm4(bl0, bl1, bl2, bl3, sBlo + boff);
            // hi*hi
            mma16816(acc[2 * np],     ah[0], ah[1], ah[2], ah[3], bh0, bh1);
            mma16816(acc[2 * np + 1], ah[0], ah[1], ah[2], ah[3], bh2, bh3);
            // hi*lo
            mma16816(acc[2 * np],     ah[0], ah[1], ah[2], ah[3], bl0, bl1);
            mma16816(acc[2 * np + 1], ah[0], ah[1], ah[2], ah[3], bl2, bl3);
            // lo*hi
            mma16816(acc[2 * np],     al[0], al[1], al[2], al[3], bh0, bh1);
            mma16816(acc[2 * np + 1], al[0], al[1], al[2], al[3], bh2, bh3);
        }

#pragma unroll
        for (int i = 0; i < 4; i++) raw[i] = nxt[i];
    }

    // --- Epilogue: C frag (lane/4, 2*(lane%4)+{0,1}) and row+8 ---
#pragma unroll
    for (int nt = 0; nt < 16; nt++) {
        int n = nt * 8 + (lane & 3) * 2;
        int sup = n >> 6;
        int nn = n & 63;
        if (p0)
            *reinterpret_cast<float2*>(
                g_presup + ((size_t)sup * N_NODES + r0) * OUT_DIM + nn) =
                make_float2(acc[nt][0], acc[nt][1]);
        if (p1)
            *reinterpret_cast<float2*>(
                g_presup + ((size_t)sup * N_NODES + r1) * OUT_DIM + nn) =
                make_float2(acc[nt][2], acc[nt][3]);
    }
}

// ---------------------------------------------------------------------------
// SpMM scatter: half-warp per edge, red.global.add.v4.f32
// ---------------------------------------------------------------------------
__global__ __launch_bounds__(256) void spmm_kernel(const float* __restrict__ edge_val,
                                                   const int* __restrict__ edge_src,
                                                   const int* __restrict__ edge_dst,
                                                   float* __restrict__ out) {
    long long t = (long long)blockIdx.x * 256 + threadIdx.x;
    long long e = t >> 4;
    if (e >= 2LL * N_EDGES) return;
    const int lane16 = (int)(t & 15);

    const float val = __ldg(edge_val + e);
    const int   src = __ldg(edge_src + e);
    const int   dst = __ldg(edge_dst + e);
    const int   sup = (e >= (long long)N_EDGES) ? 1 : 0;

    const float4 g = *reinterpret_cast<const float4*>(
        g_presup + ((size_t)sup * N_NODES + src) * OUT_DIM + lane16 * 4);

    float* oa = out + (size_t)dst * OUT_DIM + lane16 * 4;
    asm volatile("red.global.add.v4.f32 [%0], {%1, %2, %3, %4};"
                 :: "l"(oa),
                    "f"(g.x * val), "f"(g.y * val), "f"(g.z * val), "f"(g.w * val)
                 : "memory");
}

__global__ __launch_bounds__(256) void relu_kernel(float* __restrict__ out) {
    int i = blockIdx.x * 256 + threadIdx.x;
    const int n4 = N_NODES * OUT_DIM / 4;
    if (i < n4) {
        float4* p = reinterpret_cast<float4*>(out) + i;
        float4 v = *p;
        v.x = fmaxf(v.x, 0.f);
        v.y = fmaxf(v.y, 0.f);
        v.z = fmaxf(v.z, 0.f);
        v.w = fmaxf(v.w, 0.f);
        *p = v;
    }
}

extern "C" void kernel_launch(void* const* d_in, const int* in_sizes, int n_in,
                              void* d_out, int out_size) {
    const float* x        = (const float*)d_in[0];
    const float* W        = (const float*)d_in[1];
    const float* edge_val = (const float*)d_in[2];
    const int*   edge_src = (const int*)d_in[3];
    const int*   edge_dst = (const int*)d_in[4];
    float*       out      = (float*)d_out;

    cudaFuncSetAttribute(gemm_hmma, cudaFuncAttributeMaxDynamicSharedMemorySize,
                         SMEM_BYTES);

    cudaMemsetAsync(out, 0, (size_t)N_NODES * OUT_DIM * sizeof(float), 0);

    wconv_kernel<<<128, 256>>>(W);
    gemm_hmma<<<(N_NODES + 127) / 128, 256, SMEM_BYTES>>>(x);

    long long total = 2LL * N_EDGES * 16;
    int blocks = (int)((total + 255) / 256);
    spmm_kernel<<<blocks, 256>>>(edge_val, edge_src, edge_dst, out);

    relu_kernel<<<(N_NODES * OUT_DIM / 4 + 255) / 256, 256>>>(out);
}

// round 5
// speedup vs baseline: 1.7554x; 1.3235x over previous
#include <cuda_runtime.h>
#include <cuda_bf16.h>
#include <cstdint>
#include <cstddef>

#define N_NODES 100000
#define N_EDGES 1600000
#define IN_DIM 256
#define OUT_DIM 64
#define TOT_E (2 * N_EDGES)

// Static scratch (no allocations allowed).
__device__ float g_presup[2ULL * N_NODES * OUT_DIM];      // 51.2 MB
__device__ __nv_bfloat16 g_Wb_hi[128 * 256];
__device__ __nv_bfloat16 g_Wb_lo[128 * 256];
__device__ int  g_count[N_NODES];                          // histogram, then cursor
__device__ int  g_start[N_NODES];                          // exclusive scan
__device__ int  g_bsum[128];                               // per-block sums for scan
__device__ int2 g_edges[TOT_E];                            // binned {row, val} records

// ---------------------------------------------------------------------------
// W conversion: W[2][256][64] fp32 -> W^T bf16 hi/lo, [n][k] layout
// ---------------------------------------------------------------------------
__global__ void wconv_kernel(const float* __restrict__ W) {
    int t = blockIdx.x * 256 + threadIdx.x;
    if (t >= 128 * 256) return;
    int n = t >> 8, k = t & 255;
    int s = n >> 6, j = n & 63;
    float f = W[((size_t)s * IN_DIM + k) * OUT_DIM + j];
    __nv_bfloat16 h = __float2bfloat16(f);
    float lo = f - __bfloat162float(h);
    g_Wb_hi[t] = h;
    g_Wb_lo[t] = __float2bfloat16(lo);
}

// ---------------------------------------------------------------------------
// HMMA GEMM (unchanged from R3): bf16 split emulation, warp = m16 x n128.
// ---------------------------------------------------------------------------
#define BS_STRIDE 264
#define BS_BYTES  (128 * BS_STRIDE * 2)
#define SMEM_BYTES (2 * BS_BYTES)

__device__ __forceinline__ uint32_t smem_u32(const void* p) {
    uint32_t a;
    asm("{ .reg .u64 t; cvta.to.shared.u64 t, %1; cvt.u32.u64 %0, t; }" : "=r"(a) : "l"(p));
    return a;
}
__device__ __forceinline__ void ldsm4(uint32_t& d0, uint32_t& d1, uint32_t& d2,
                                      uint32_t& d3, uint32_t addr) {
    asm volatile("ldmatrix.sync.aligned.m8n8.x4.shared.b16 {%0,%1,%2,%3}, [%4];"
                 : "=r"(d0), "=r"(d1), "=r"(d2), "=r"(d3) : "r"(addr));
}
__device__ __forceinline__ void mma16816(float* c, uint32_t a0, uint32_t a1,
                                         uint32_t a2, uint32_t a3,
                                         uint32_t b0, uint32_t b1) {
    asm volatile(
        "mma.sync.aligned.m16n8k16.row.col.f32.bf16.bf16.f32 "
        "{%0,%1,%2,%3}, {%4,%5,%6,%7}, {%8,%9}, {%0,%1,%2,%3};"
        : "+f"(c[0]), "+f"(c[1]), "+f"(c[2]), "+f"(c[3])
        : "r"(a0), "r"(a1), "r"(a2), "r"(a3), "r"(b0), "r"(b1));
}
__device__ __forceinline__ uint32_t pack_hi(float a, float b) {
    __nv_bfloat162 h = __floats2bfloat162_rn(a, b);
    return *reinterpret_cast<uint32_t*>(&h);
}
__device__ __forceinline__ uint32_t pack_lo(float a, float b, uint32_t hi) {
    __nv_bfloat162 h = *reinterpret_cast<__nv_bfloat162*>(&hi);
    __nv_bfloat162 l = __floats2bfloat162_rn(a - __bfloat162float(h.x),
                                             b - __bfloat162float(h.y));
    return *reinterpret_cast<uint32_t*>(&l);
}

__global__ __launch_bounds__(256, 1) void gemm_hmma(const float* __restrict__ x) {
    extern __shared__ __align__(16) char smem[];
    const uint32_t sBhi = smem_u32(smem);
    const uint32_t sBlo = sBhi + BS_BYTES;
    const int tid = threadIdx.x;
    const int wid = tid >> 5;
    const int lane = tid & 31;

#pragma unroll 4
    for (int it = 0; it < 16; it++) {
        int idx = it * 256 + tid;
        int n = idx >> 5;
        int kq = (idx & 31) * 8;
        uint32_t off = (uint32_t)(n * BS_STRIDE + kq) * 2;
        *reinterpret_cast<uint4*>(smem + off) =
            *reinterpret_cast<const uint4*>(g_Wb_hi + n * 256 + kq);
        *reinterpret_cast<uint4*>(smem + BS_BYTES + off) =
            *reinterpret_cast<const uint4*>(g_Wb_lo + n * 256 + kq);
    }
    __syncthreads();

    const int m_base = blockIdx.x * 128 + wid * 16;
    const int r0 = m_base + (lane >> 2);
    const int r1 = r0 + 8;
    const bool p0 = r0 < N_NODES;
    const bool p1 = r1 < N_NODES;
    const float* x0 = x + (size_t)(p0 ? r0 : 0) * IN_DIM;
    const float* x1 = x + (size_t)(p1 ? r1 : 0) * IN_DIM;
    const int klane = (lane & 3) * 2;

    const int grp = lane >> 3;
    const int lrow = lane & 7;
    const uint32_t b_off = (uint32_t)((lrow + ((grp & 2) << 2)) * BS_STRIDE +
                                      ((grp & 1) << 3)) * 2;

    float acc[16][4];
#pragma unroll
    for (int i = 0; i < 16; i++)
#pragma unroll
        for (int j = 0; j < 4; j++) acc[i][j] = 0.f;

    float2 raw[4];
    raw[0] = *reinterpret_cast<const float2*>(x0 + klane);
    raw[1] = *reinterpret_cast<const float2*>(x1 + klane);
    raw[2] = *reinterpret_cast<const float2*>(x0 + klane + 8);
    raw[3] = *reinterpret_cast<const float2*>(x1 + klane + 8);

    for (int kk = 0; kk < 16; kk++) {
        float2 nxt[4];
        if (kk < 15) {
            int k0 = (kk + 1) * 16 + klane;
            nxt[0] = *reinterpret_cast<const float2*>(x0 + k0);
            nxt[1] = *reinterpret_cast<const float2*>(x1 + k0);
            nxt[2] = *reinterpret_cast<const float2*>(x0 + k0 + 8);
            nxt[3] = *reinterpret_cast<const float2*>(x1 + k0 + 8);
        }

        uint32_t ah[4], al[4];
#pragma unroll
        for (int i = 0; i < 4; i++) {
            ah[i] = pack_hi(raw[i].x, raw[i].y);
            al[i] = pack_lo(raw[i].x, raw[i].y, ah[i]);
        }

        const uint32_t kbyte = (uint32_t)(kk * 16) * 2 + b_off;
#pragma unroll
        for (int np = 0; np < 8; np++) {
            const uint32_t boff = kbyte + (uint32_t)(np * 16 * BS_STRIDE) * 2;
            uint32_t bh0, bh1, bh2, bh3, bl0, bl1, bl2, bl3;
            ldsm4(bh0, bh1, bh2, bh3, sBhi + boff);
            ldsm4(bl0, bl1, bl2, bl3, sBlo + boff);
            mma16816(acc[2 * np],     ah[0], ah[1], ah[2], ah[3], bh0, bh1);
            mma16816(acc[2 * np + 1], ah[0], ah[1], ah[2], ah[3], bh2, bh3);
            mma16816(acc[2 * np],     ah[0], ah[1], ah[2], ah[3], bl0, bl1);
            mma16816(acc[2 * np + 1], ah[0], ah[1], ah[2], ah[3], bl2, bl3);
            mma16816(acc[2 * np],     al[0], al[1], al[2], al[3], bh0, bh1);
            mma16816(acc[2 * np + 1], al[0], al[1], al[2], al[3], bh2, bh3);
        }
#pragma unroll
        for (int i = 0; i < 4; i++) raw[i] = nxt[i];
    }

#pragma unroll
    for (int nt = 0; nt < 16; nt++) {
        int n = nt * 8 + (lane & 3) * 2;
        int sup = n >> 6;
        int nn = n & 63;
        if (p0)
            *reinterpret_cast<float2*>(
                g_presup + ((size_t)sup * N_NODES + r0) * OUT_DIM + nn) =
                make_float2(acc[nt][0], acc[nt][1]);
        if (p1)
            *reinterpret_cast<float2*>(
                g_presup + ((size_t)sup * N_NODES + r1) * OUT_DIM + nn) =
                make_float2(acc[nt][2], acc[nt][3]);
    }
}

// ---------------------------------------------------------------------------
// dst-binning: histogram -> exclusive scan -> permute into packed records
// ---------------------------------------------------------------------------
__global__ __launch_bounds__(256) void zero_kernel() {
    int t = blockIdx.x * 256 + threadIdx.x;
    if (t < N_NODES) g_count[t] = 0;
}

__global__ __launch_bounds__(256) void hist_kernel(const int* __restrict__ edge_dst) {
    int t = blockIdx.x * 256 + threadIdx.x;
    if (t < TOT_E) atomicAdd(&g_count[__ldg(edge_dst + t)], 1);
}

// scan1: per-1024-block local exclusive scan + block sums
__global__ __launch_bounds__(256) void scan1_kernel() {
    __shared__ int wsum[8];
    const int tid = threadIdx.x;
    const int base = blockIdx.x * 1024 + tid * 4;
    int v[4];
#pragma unroll
    for (int j = 0; j < 4; j++)
        v[j] = (base + j < N_NODES) ? g_count[base + j] : 0;
    int t1 = v[0], t2 = v[0] + v[1], t3 = t2 + v[2];
    int tot = t3 + v[3];

    int lane = tid & 31, w = tid >> 5;
    int inc = tot;
#pragma unroll
    for (int d = 1; d < 32; d <<= 1) {
        int n = __shfl_up_sync(0xFFFFFFFF, inc, d);
        if (lane >= d) inc += n;
    }
    int excl = inc - tot;
    if (lane == 31) wsum[w] = inc;
    __syncthreads();
    if (tid == 0) {
        int run = 0;
#pragma unroll
        for (int k = 0; k < 8; k++) { int tmp = wsum[k]; wsum[k] = run; run += tmp; }
        g_bsum[blockIdx.x] = run;
    }
    __syncthreads();
    int off = wsum[w] + excl;
    if (base + 0 < N_NODES) g_start[base + 0] = off;
    if (base + 1 < N_NODES) g_start[base + 1] = off + t1;
    if (base + 2 < N_NODES) g_start[base + 2] = off + t2;
    if (base + 3 < N_NODES) g_start[base + 3] = off + t3;
}

__global__ void scan2_kernel(int nb) {
    int run = 0;
    for (int k = 0; k < nb; k++) { int tmp = g_bsum[k]; g_bsum[k] = run; run += tmp; }
}

__global__ __launch_bounds__(256) void scan3_kernel() {
    int t = blockIdx.x * 256 + threadIdx.x;
    if (t < N_NODES) {
        int s = g_start[t] + g_bsum[t >> 10];
        g_start[t] = s;
        g_count[t] = s;   // reuse as running cursor for permute
    }
}

__global__ __launch_bounds__(256) void permute_kernel(const float* __restrict__ edge_val,
                                                      const int* __restrict__ edge_src,
                                                      const int* __restrict__ edge_dst) {
    int t = blockIdx.x * 256 + threadIdx.x;
    if (t >= TOT_E) return;
    int dst = __ldg(edge_dst + t);
    int src = __ldg(edge_src + t);
    float val = __ldg(edge_val + t);
    int row = src + ((t >= N_EDGES) ? N_NODES : 0);
    int pos = atomicAdd(&g_count[dst], 1);
    g_edges[pos] = make_int2(row, __float_as_int(val));
}

// ---------------------------------------------------------------------------
// Aggregate: half-warp (16 lanes) per node; register accumulation + fused ReLU
// ---------------------------------------------------------------------------
__global__ __launch_bounds__(256) void aggregate_kernel(float* __restrict__ out) {
    int t = blockIdx.x * 256 + threadIdx.x;
    int node = t >> 4;
    if (node >= N_NODES) return;
    const int lane16 = t & 15;

    int i   = g_start[node];
    int end = g_count[node];   // cursor after permute == start[node] + count[node]

    float4 acc = make_float4(0.f, 0.f, 0.f, 0.f);

    for (; i + 1 < end; i += 2) {
        int2 r0 = __ldg(g_edges + i);
        int2 r1 = __ldg(g_edges + i + 1);
        const float4 gA = *reinterpret_cast<const float4*>(
            g_presup + (size_t)r0.x * OUT_DIM + lane16 * 4);
        const float4 gB = *reinterpret_cast<const float4*>(
            g_presup + (size_t)r1.x * OUT_DIM + lane16 * 4);
        float v0 = __int_as_float(r0.y);
        float v1 = __int_as_float(r1.y);
        acc.x = fmaf(v0, gA.x, acc.x); acc.y = fmaf(v0, gA.y, acc.y);
        acc.z = fmaf(v0, gA.z, acc.z); acc.w = fmaf(v0, gA.w, acc.w);
        acc.x = fmaf(v1, gB.x, acc.x); acc.y = fmaf(v1, gB.y, acc.y);
        acc.z = fmaf(v1, gB.z, acc.z); acc.w = fmaf(v1, gB.w, acc.w);
    }
    if (i < end) {
        int2 r0 = __ldg(g_edges + i);
        const float4 gA = *reinterpret_cast<const float4*>(
            g_presup + (size_t)r0.x * OUT_DIM + lane16 * 4);
        float v0 = __int_as_float(r0.y);
        acc.x = fmaf(v0, gA.x, acc.x); acc.y = fmaf(v0, gA.y, acc.y);
        acc.z = fmaf(v0, gA.z, acc.z); acc.w = fmaf(v0, gA.w, acc.w);
    }

    acc.x = fmaxf(acc.x, 0.f); acc.y = fmaxf(acc.y, 0.f);
    acc.z = fmaxf(acc.z, 0.f); acc.w = fmaxf(acc.w, 0.f);
    *reinterpret_cast<float4*>(out + (size_t)node * OUT_DIM + lane16 * 4) = acc;
}

extern "C" void kernel_launch(void* const* d_in, const int* in_sizes, int n_in,
                              void* d_out, int out_size) {
    const float* x        = (const float*)d_in[0];
    const float* W        = (const float*)d_in[1];
    const float* edge_val = (const float*)d_in[2];
    const int*   edge_src = (const int*)d_in[3];
    const int*   edge_dst = (const int*)d_in[4];
    float*       out      = (float*)d_out;

    cudaFuncSetAttribute(gemm_hmma, cudaFuncAttributeMaxDynamicSharedMemorySize,
                         SMEM_BYTES);

    const int nb_scan = (N_NODES + 1023) / 1024;   // 98

    wconv_kernel<<<128, 256>>>(W);
    gemm_hmma<<<(N_NODES + 127) / 128, 256, SMEM_BYTES>>>(x);

    zero_kernel<<<(N_NODES + 255) / 256, 256>>>();
    hist_kernel<<<(TOT_E + 255) / 256, 256>>>(edge_dst);
    scan1_kernel<<<nb_scan, 256>>>();
    scan2_kernel<<<1, 1>>>(nb_scan);
    scan3_kernel<<<(N_NODES + 255) / 256, 256>>>();
    permute_kernel<<<(TOT_E + 255) / 256, 256>>>(edge_val, edge_src, edge_dst);

    aggregate_kernel<<<(N_NODES * 16 + 255) / 256, 256>>>(out);
}